// round 9
// baseline (speedup 1.0000x reference)
#include <cuda_runtime.h>
#include <math.h>

#define BB 2
#define NN 512
#define CC 256
#define OUTSZ 14
#define POOL_PER_BOX (CC * OUTSZ * OUTSZ)   // 50176
#define NPOS (OUTSZ * OUTSZ)                // 196
#define NMS_THRC 0.5f
#define CHALF (CC / 2)                      // 128 channels per pool block

// Scratch (no allocations allowed)
__device__ float g_verts[BB * NN * 4];      // original order
__device__ int   g_level[BB * NN];          // original order
__device__ int   g_keep [BB * NN];          // original order

// ---------------------------------------------------------------------------
// Kernel 1: fully fused NMS. Grid = BB, 512 threads.
//   rank-by-counting stable sort -> smem mask build -> ffs greedy scan
//   -> keep/out_boxes tail writes.
// ---------------------------------------------------------------------------
__global__ __launch_bounds__(NN) void nms_kernel(const float* __restrict__ boxes,
                                                 const float* __restrict__ scores,
                                                 float* __restrict__ out)
{
    const int b   = blockIdx.x;
    const int tid = threadIdx.x;

    __shared__ float         sscore[NN];
    __shared__ float4        sbox[NN];       // sorted order
    __shared__ float         sarea[NN];
    __shared__ unsigned char slev[NN];
    __shared__ short         sord[NN];       // sorted rank -> original idx
    __shared__ unsigned      smask[NN][16];  // 32 KB
    __shared__ unsigned      keepw_s[16];

    // --- verts + level ---
    const float* bbp = boxes + (size_t)b * NN * 4;
    float cx = bbp[tid * 4 + 0];
    float cy = bbp[tid * 4 + 1];
    float w  = bbp[tid * 4 + 2];
    float h  = bbp[tid * 4 + 3];
    float x1 = cx - w * 0.5f;
    float y1 = cy - h * 0.5f;
    float x2 = cx + w * 0.5f;
    float y2 = cy + h * 0.5f;

    float lv = floorf(3.0f + log2f(sqrtf(w * h) / 224.0f));
    lv = fminf(fmaxf(lv, 1.0f), 4.0f);
    int lev = (int)lv;

    int gi = b * NN + tid;
    g_verts[gi * 4 + 0] = x1;
    g_verts[gi * 4 + 1] = y1;
    g_verts[gi * 4 + 2] = x2;
    g_verts[gi * 4 + 3] = y2;
    g_level[gi] = lev;

    float ms = scores[gi];
    sscore[tid] = ms;
    __syncthreads();

    // --- stable descending rank by counting (no sort network) ---
    int r = 0;
    #pragma unroll 8
    for (int j = 0; j < NN; j++) {
        float sj = sscore[j];               // warp-broadcast LDS
        r += (sj > ms) || (sj == ms && j < tid);
    }

    // scatter my box into sorted position r
    sbox [r] = make_float4(x1, y1, x2, y2);
    sarea[r] = (x2 - x1) * (y2 - y1);
    slev [r] = (unsigned char)lev;
    sord [r] = (short)tid;
    __syncthreads();

    // --- suppression-matrix row for sorted rank tid ---
    {
        float4 mb = sbox[tid];
        float  marea = sarea[tid];
        unsigned char mylev = slev[tid];
        const int myw = tid >> 5;
        for (int wq = 0; wq < myw; wq++) smask[tid][wq] = 0u;
        for (int wq = myw; wq < 16; wq++) {
            unsigned bits = 0u;
            #pragma unroll
            for (int jb = 0; jb < 32; jb++) {
                int j = (wq << 5) + jb;
                float4 ob = sbox[j];
                float ix1 = fmaxf(mb.x, ob.x);
                float iy1 = fmaxf(mb.y, ob.y);
                float ix2 = fminf(mb.z, ob.z);
                float iy2 = fminf(mb.w, ob.w);
                float iw = fmaxf(ix2 - ix1, 0.0f);
                float ih = fmaxf(iy2 - iy1, 0.0f);
                float inter = iw * ih;
                float iou = inter / (marea + sarea[j] - inter + 1e-9f);
                bool sup = (j > tid) && (slev[j] == mylev) && (iou > NMS_THRC);
                bits |= ((unsigned)sup) << jb;
            }
            smask[tid][wq] = bits;
        }
    }
    __syncthreads();

    // --- greedy scan: single warp, ffs-skip over kept boxes ---
    if (tid < 32) {
        int wl = tid & 15;
        unsigned kw = 0xFFFFFFFFu;
        for (int wq = 0; wq < 16; wq++) {
            unsigned cur = __shfl_sync(0xffffffffu, kw, wq);
            while (cur) {
                int bq = __ffs(cur) - 1;
                int row = (wq << 5) + bq;
                unsigned mw = smask[row][wl];   // broadcast LDS
                unsigned mq = smask[row][wq];   // broadcast LDS
                cur &= ~(mq | (1u << bq));
                kw  &= ~mw;
            }
        }
        if (tid < 16) keepw_s[tid] = kw;
    }
    __syncthreads();

    // --- keep + tail writes (tid is a sorted rank here) ---
    int kept = (keepw_s[tid >> 5] >> (tid & 31)) & 1;
    int o   = sord[tid];
    int go  = b * NN + o;
    g_keep[go] = kept;

    float4 sb = sbox[tid];
    float* ob = out + (size_t)BB * NN * POOL_PER_BOX;
    float* ok = ob + (size_t)BB * NN * 4;
    ob[go * 4 + 0] = kept ? sb.x : 0.0f;
    ob[go * 4 + 1] = kept ? sb.y : 0.0f;
    ob[go * 4 + 2] = kept ? sb.z : 0.0f;
    ob[go * 4 + 3] = kept ? sb.w : 0.0f;
    ok[go] = kept ? 1.0f : 0.0f;
}

// ---------------------------------------------------------------------------
// Kernel 2: ROI align. TWO blocks per box (channel halves) for load balance.
// Thread t < 196 owns one output position; 16 offsets + 16 pre-scaled
// weights in registers; 128-channel loop of pure __ldg + coalesced store.
// ---------------------------------------------------------------------------
__global__ __launch_bounds__(256, 4) void pool_kernel(const float* __restrict__ p4,
                                                      const float* __restrict__ p8,
                                                      const float* __restrict__ p16,
                                                      const float* __restrict__ p32,
                                                      float* __restrict__ out)
{
    const int bn   = blockIdx.x >> 1;       // box index
    const int half = blockIdx.x & 1;        // channel half
    const int b    = bn / NN;
    const int tid  = threadIdx.x;

    float* o = out + (size_t)bn * POOL_PER_BOX + (size_t)half * CHALF * NPOS;

    if (!g_keep[bn]) {
        float4* o4 = (float4*)o;
        float4 z = make_float4(0.f, 0.f, 0.f, 0.f);
        #pragma unroll 4
        for (int i = tid; i < CHALF * NPOS / 4; i += 256) o4[i] = z;
        return;
    }
    if (tid >= NPOS) return;

    const int lev = g_level[bn];
    const float* feat;
    int H;
    float stride;
    if (lev == 1)      { feat = p4;  H = 256; stride = 4.0f;  }
    else if (lev == 2) { feat = p8;  H = 128; stride = 8.0f;  }
    else if (lev == 3) { feat = p16; H = 64;  stride = 16.0f; }
    else               { feat = p32; H = 32;  stride = 32.0f; }
    const int W  = H;
    const int HW = H * W;

    float inv = 1.0f / stride;
    float rx1 = g_verts[bn * 4 + 0] * inv;
    float ry1 = g_verts[bn * 4 + 1] * inv;
    float rx2 = g_verts[bn * 4 + 2] * inv;
    float ry2 = g_verts[bn * 4 + 3] * inv;
    float bw = (rx2 - rx1) / (float)OUTSZ;
    float bh = (ry2 - ry1) / (float)OUTSZ;

    const int oy = tid / OUTSZ;
    const int ox = tid - oy * OUTSZ;

    int   cofs[4];
    float wx[4];
    #pragma unroll
    for (int j = 0; j < 2; j++) {
        float g  = ((float)(2 * ox + j) + 0.5f) * 0.5f;
        float xs = fminf(fmaxf(rx1 + g * bw, 0.0f), (float)W - 1.0f);
        float x0f = floorf(xs);
        int   x0  = (int)x0f;
        float lx  = xs - x0f;
        cofs[2 * j]     = x0;
        cofs[2 * j + 1] = min(x0 + 1, W - 1);
        wx[2 * j]       = 1.0f - lx;
        wx[2 * j + 1]   = lx;
    }
    int   rofs[4];
    float wy[4];
    #pragma unroll
    for (int j = 0; j < 2; j++) {
        float g  = ((float)(2 * oy + j) + 0.5f) * 0.5f;
        float ys = fminf(fmaxf(ry1 + g * bh, 0.0f), (float)H - 1.0f);
        float y0f = floorf(ys);
        int   y0  = (int)y0f;
        float ly  = ys - y0f;
        rofs[2 * j]     = y0 * W;
        rofs[2 * j + 1] = min(y0 + 1, H - 1) * W;
        wy[2 * j]       = 0.25f * (1.0f - ly);
        wy[2 * j + 1]   = 0.25f * ly;
    }

    int   off[16];
    float wxy[16];
    #pragma unroll
    for (int k = 0; k < 4; k++)
        #pragma unroll
        for (int l = 0; l < 4; l++) {
            off[k * 4 + l] = rofs[k] + cofs[l];
            wxy[k * 4 + l] = wy[k] * wx[l];
        }

    const float* fp = feat + (size_t)b * CC * HW + (size_t)half * CHALF * HW;
    float* op = o + tid;

    #pragma unroll 1
    for (int c = 0; c < CHALF; c++) {
        float a0 = wxy[0]  * __ldg(fp + off[0]);
        float a1 = wxy[1]  * __ldg(fp + off[1]);
        float a2 = wxy[2]  * __ldg(fp + off[2]);
        float a3 = wxy[3]  * __ldg(fp + off[3]);
        a0 = fmaf(wxy[4],  __ldg(fp + off[4]),  a0);
        a1 = fmaf(wxy[5],  __ldg(fp + off[5]),  a1);
        a2 = fmaf(wxy[6],  __ldg(fp + off[6]),  a2);
        a3 = fmaf(wxy[7],  __ldg(fp + off[7]),  a3);
        a0 = fmaf(wxy[8],  __ldg(fp + off[8]),  a0);
        a1 = fmaf(wxy[9],  __ldg(fp + off[9]),  a1);
        a2 = fmaf(wxy[10], __ldg(fp + off[10]), a2);
        a3 = fmaf(wxy[11], __ldg(fp + off[11]), a3);
        a0 = fmaf(wxy[12], __ldg(fp + off[12]), a0);
        a1 = fmaf(wxy[13], __ldg(fp + off[13]), a1);
        a2 = fmaf(wxy[14], __ldg(fp + off[14]), a2);
        a3 = fmaf(wxy[15], __ldg(fp + off[15]), a3);
        op[c * NPOS] = (a0 + a1) + (a2 + a3);
        fp += HW;
    }
}

extern "C" void kernel_launch(void* const* d_in, const int* in_sizes, int n_in,
                              void* d_out, int out_size)
{
    const float* p4     = (const float*)d_in[0];
    const float* p8     = (const float*)d_in[1];
    const float* p16    = (const float*)d_in[2];
    const float* p32    = (const float*)d_in[3];
    const float* boxes  = (const float*)d_in[4];
    const float* scores = (const float*)d_in[5];
    float* out = (float*)d_out;

    nms_kernel<<<BB, NN>>>(boxes, scores, out);
    pool_kernel<<<BB * NN * 2, 256>>>(p4, p8, p16, p32, out);
}

// round 10
// speedup vs baseline: 1.1615x; 1.1615x over previous
#include <cuda_runtime.h>
#include <math.h>

#define BB 2
#define NN 512
#define CC 256
#define OUTSZ 14
#define POOL_PER_BOX (CC * OUTSZ * OUTSZ)   // 50176
#define NPOS (OUTSZ * OUTSZ)                // 196
#define NMS_THRC 0.5f
#define CHALF (CC / 2)                      // 128 channels per pool block
#define PSZ 768                             // patch floats per channel (bound ~510)

// Scratch (no allocations allowed)
__device__ float g_verts[BB * NN * 4];      // original order
__device__ int   g_level[BB * NN];          // original order
__device__ int   g_keep [BB * NN];          // original order

// ---------------------------------------------------------------------------
// Kernel 1: fully fused NMS. Grid = BB, 512 threads. (Known-good from R9.)
// ---------------------------------------------------------------------------
__global__ __launch_bounds__(NN) void nms_kernel(const float* __restrict__ boxes,
                                                 const float* __restrict__ scores,
                                                 float* __restrict__ out)
{
    const int b   = blockIdx.x;
    const int tid = threadIdx.x;

    __shared__ float         sscore[NN];
    __shared__ float4        sbox[NN];
    __shared__ float         sarea[NN];
    __shared__ unsigned char slev[NN];
    __shared__ short         sord[NN];
    __shared__ unsigned      smask[NN][16];
    __shared__ unsigned      keepw_s[16];

    const float* bbp = boxes + (size_t)b * NN * 4;
    float cx = bbp[tid * 4 + 0];
    float cy = bbp[tid * 4 + 1];
    float w  = bbp[tid * 4 + 2];
    float h  = bbp[tid * 4 + 3];
    float x1 = cx - w * 0.5f;
    float y1 = cy - h * 0.5f;
    float x2 = cx + w * 0.5f;
    float y2 = cy + h * 0.5f;

    float lv = floorf(3.0f + log2f(sqrtf(w * h) / 224.0f));
    lv = fminf(fmaxf(lv, 1.0f), 4.0f);
    int lev = (int)lv;

    int gi = b * NN + tid;
    g_verts[gi * 4 + 0] = x1;
    g_verts[gi * 4 + 1] = y1;
    g_verts[gi * 4 + 2] = x2;
    g_verts[gi * 4 + 3] = y2;
    g_level[gi] = lev;

    float ms = scores[gi];
    sscore[tid] = ms;
    __syncthreads();

    // stable descending rank by counting
    int r = 0;
    #pragma unroll 8
    for (int j = 0; j < NN; j++) {
        float sj = sscore[j];
        r += (sj > ms) || (sj == ms && j < tid);
    }

    sbox [r] = make_float4(x1, y1, x2, y2);
    sarea[r] = (x2 - x1) * (y2 - y1);
    slev [r] = (unsigned char)lev;
    sord [r] = (short)tid;
    __syncthreads();

    // suppression-matrix row for sorted rank tid
    {
        float4 mb = sbox[tid];
        float  marea = sarea[tid];
        unsigned char mylev = slev[tid];
        const int myw = tid >> 5;
        for (int wq = 0; wq < myw; wq++) smask[tid][wq] = 0u;
        for (int wq = myw; wq < 16; wq++) {
            unsigned bits = 0u;
            #pragma unroll
            for (int jb = 0; jb < 32; jb++) {
                int j = (wq << 5) + jb;
                float4 ob = sbox[j];
                float ix1 = fmaxf(mb.x, ob.x);
                float iy1 = fmaxf(mb.y, ob.y);
                float ix2 = fminf(mb.z, ob.z);
                float iy2 = fminf(mb.w, ob.w);
                float iw = fmaxf(ix2 - ix1, 0.0f);
                float ih = fmaxf(iy2 - iy1, 0.0f);
                float inter = iw * ih;
                float iou = inter / (marea + sarea[j] - inter + 1e-9f);
                bool sup = (j > tid) && (slev[j] == mylev) && (iou > NMS_THRC);
                bits |= ((unsigned)sup) << jb;
            }
            smask[tid][wq] = bits;
        }
    }
    __syncthreads();

    // greedy scan: single warp, ffs-skip over kept boxes
    if (tid < 32) {
        int wl = tid & 15;
        unsigned kw = 0xFFFFFFFFu;
        for (int wq = 0; wq < 16; wq++) {
            unsigned cur = __shfl_sync(0xffffffffu, kw, wq);
            while (cur) {
                int bq = __ffs(cur) - 1;
                int row = (wq << 5) + bq;
                unsigned mw = smask[row][wl];
                unsigned mq = smask[row][wq];
                cur &= ~(mq | (1u << bq));
                kw  &= ~mw;
            }
        }
        if (tid < 16) keepw_s[tid] = kw;
    }
    __syncthreads();

    int kept = (keepw_s[tid >> 5] >> (tid & 31)) & 1;
    int o   = sord[tid];
    int go  = b * NN + o;
    g_keep[go] = kept;

    float4 sb = sbox[tid];
    float* ob = out + (size_t)BB * NN * POOL_PER_BOX;
    float* ok = ob + (size_t)BB * NN * 4;
    ob[go * 4 + 0] = kept ? sb.x : 0.0f;
    ob[go * 4 + 1] = kept ? sb.y : 0.0f;
    ob[go * 4 + 2] = kept ? sb.z : 0.0f;
    ob[go * 4 + 3] = kept ? sb.w : 0.0f;
    ok[go] = kept ? 1.0f : 0.0f;
}

// ---------------------------------------------------------------------------
// Kernel 2: ROI align via per-channel SMEM patch, double-buffered.
// Two blocks per box (channel halves). Thread t<196 owns one output pos;
// taps come from LDS; staging is coalesced LDG with precomputed offsets.
// Fallback to direct gather if the patch exceeds PSZ (uniform per block).
// ---------------------------------------------------------------------------
__global__ __launch_bounds__(256) void pool_kernel(const float* __restrict__ p4,
                                                   const float* __restrict__ p8,
                                                   const float* __restrict__ p16,
                                                   const float* __restrict__ p32,
                                                   float* __restrict__ out)
{
    const int bn   = blockIdx.x >> 1;
    const int half = blockIdx.x & 1;
    const int b    = bn / NN;
    const int tid  = threadIdx.x;

    float* o = out + (size_t)bn * POOL_PER_BOX + (size_t)half * CHALF * NPOS;

    if (!g_keep[bn]) {
        float4* o4 = (float4*)o;
        float4 z = make_float4(0.f, 0.f, 0.f, 0.f);
        #pragma unroll 4
        for (int i = tid; i < CHALF * NPOS / 4; i += 256) o4[i] = z;
        return;
    }

    const int lev = g_level[bn];
    const float* feat;
    int H;
    float stride;
    if (lev == 1)      { feat = p4;  H = 256; stride = 4.0f;  }
    else if (lev == 2) { feat = p8;  H = 128; stride = 8.0f;  }
    else if (lev == 3) { feat = p16; H = 64;  stride = 16.0f; }
    else               { feat = p32; H = 32;  stride = 32.0f; }
    const int W  = H;
    const int HW = H * W;

    float inv = 1.0f / stride;
    float rx1 = g_verts[bn * 4 + 0] * inv;
    float ry1 = g_verts[bn * 4 + 1] * inv;
    float ry2 = g_verts[bn * 4 + 3] * inv;
    float rx2 = g_verts[bn * 4 + 2] * inv;
    float bw = (rx2 - rx1) / (float)OUTSZ;
    float bh = (ry2 - ry1) / (float)OUTSZ;

    // Uniform patch bounds (samples are monotone in index)
    float xsf = fminf(fmaxf(rx1 + 0.25f  * bw, 0.0f), (float)W - 1.0f);
    float xsl = fminf(fmaxf(rx1 + 13.75f * bw, 0.0f), (float)W - 1.0f);
    float ysf = fminf(fmaxf(ry1 + 0.25f  * bh, 0.0f), (float)H - 1.0f);
    float ysl = fminf(fmaxf(ry1 + 13.75f * bh, 0.0f), (float)H - 1.0f);
    const int xmin  = (int)floorf(xsf);
    const int xmax  = min((int)floorf(xsl) + 1, W - 1);
    const int ymin  = (int)floorf(ysf);
    const int ymax  = min((int)floorf(ysl) + 1, H - 1);
    const int pcols = xmax - xmin + 1;
    const int prows = ymax - ymin + 1;
    const int pp    = prows * pcols;

    // Per-thread sample data (absolute)
    const int oy = (tid < NPOS) ? (tid / OUTSZ) : 0;
    const int ox = (tid < NPOS) ? (tid - oy * OUTSZ) : 0;

    int   x0a[2], x1a[2];
    float wx[4];
    #pragma unroll
    for (int j = 0; j < 2; j++) {
        float g  = ((float)(2 * ox + j) + 0.5f) * 0.5f;
        float xs = fminf(fmaxf(rx1 + g * bw, 0.0f), (float)W - 1.0f);
        float x0f = floorf(xs);
        int   x0  = (int)x0f;
        float lx  = xs - x0f;
        x0a[j] = x0;
        x1a[j] = min(x0 + 1, W - 1);
        wx[2 * j]     = 1.0f - lx;
        wx[2 * j + 1] = lx;
    }
    int   y0a[2], y1a[2];
    float wy[4];
    #pragma unroll
    for (int j = 0; j < 2; j++) {
        float g  = ((float)(2 * oy + j) + 0.5f) * 0.5f;
        float ys = fminf(fmaxf(ry1 + g * bh, 0.0f), (float)H - 1.0f);
        float y0f = floorf(ys);
        int   y0  = (int)y0f;
        float ly  = ys - y0f;
        y0a[j] = y0;
        y1a[j] = min(y0 + 1, H - 1);
        wy[2 * j]     = 0.25f * (1.0f - ly);
        wy[2 * j + 1] = 0.25f * ly;
    }

    const float* fp0 = feat + ((size_t)b * CC + (size_t)half * CHALF) * HW;
    float* op = o + tid;

    if (pp <= PSZ) {
        // ---------------- SMEM patch path ----------------
        __shared__ float patch[2][PSZ];

        // relative tap offsets + fused weights (registers)
        int   off[16];
        float wxy[16];
        {
            int ry[4] = { (y0a[0] - ymin) * pcols, (y1a[0] - ymin) * pcols,
                          (y0a[1] - ymin) * pcols, (y1a[1] - ymin) * pcols };
            int rx[4] = { x0a[0] - xmin, x1a[0] - xmin,
                          x0a[1] - xmin, x1a[1] - xmin };
            #pragma unroll
            for (int k = 0; k < 4; k++)
                #pragma unroll
                for (int l = 0; l < 4; l++) {
                    off[k * 4 + l] = ry[k] + rx[l];
                    wxy[k * 4 + l] = wy[k] * wx[l];
                }
        }

        // staging offsets (channel-invariant): up to 3 elements per thread
        int so[3], po[3];
        bool sv[3];
        #pragma unroll
        for (int s = 0; s < 3; s++) {
            int i = tid + s * 256;
            sv[s] = (i < pp);
            int py = i / pcols;
            int px = i - py * pcols;
            po[s] = i;
            so[s] = (ymin + py) * W + (xmin + px);
        }

        // prologue: stage channel 0 into buf 0
        {
            const float* fc = fp0;
            #pragma unroll
            for (int s = 0; s < 3; s++)
                if (sv[s]) patch[0][po[s]] = __ldg(fc + so[s]);
        }
        __syncthreads();

        #pragma unroll 1
        for (int c = 0; c < CHALF; c += 2) {
            // stage c+1 into buf1 while computing c from buf0
            if (c + 1 < CHALF) {
                const float* fc = fp0 + (size_t)(c + 1) * HW;
                #pragma unroll
                for (int s = 0; s < 3; s++)
                    if (sv[s]) patch[1][po[s]] = __ldg(fc + so[s]);
            }
            if (tid < NPOS) {
                const float* P = patch[0];
                float a0 = wxy[0]  * P[off[0]];
                float a1 = wxy[1]  * P[off[1]];
                float a2 = wxy[2]  * P[off[2]];
                float a3 = wxy[3]  * P[off[3]];
                a0 = fmaf(wxy[4],  P[off[4]],  a0);
                a1 = fmaf(wxy[5],  P[off[5]],  a1);
                a2 = fmaf(wxy[6],  P[off[6]],  a2);
                a3 = fmaf(wxy[7],  P[off[7]],  a3);
                a0 = fmaf(wxy[8],  P[off[8]],  a0);
                a1 = fmaf(wxy[9],  P[off[9]],  a1);
                a2 = fmaf(wxy[10], P[off[10]], a2);
                a3 = fmaf(wxy[11], P[off[11]], a3);
                a0 = fmaf(wxy[12], P[off[12]], a0);
                a1 = fmaf(wxy[13], P[off[13]], a1);
                a2 = fmaf(wxy[14], P[off[14]], a2);
                a3 = fmaf(wxy[15], P[off[15]], a3);
                op[c * NPOS] = (a0 + a1) + (a2 + a3);
            }
            __syncthreads();

            if (c + 1 < CHALF) {
                // stage c+2 into buf0 while computing c+1 from buf1
                if (c + 2 < CHALF) {
                    const float* fc = fp0 + (size_t)(c + 2) * HW;
                    #pragma unroll
                    for (int s = 0; s < 3; s++)
                        if (sv[s]) patch[0][po[s]] = __ldg(fc + so[s]);
                }
                if (tid < NPOS) {
                    const float* P = patch[1];
                    float a0 = wxy[0]  * P[off[0]];
                    float a1 = wxy[1]  * P[off[1]];
                    float a2 = wxy[2]  * P[off[2]];
                    float a3 = wxy[3]  * P[off[3]];
                    a0 = fmaf(wxy[4],  P[off[4]],  a0);
                    a1 = fmaf(wxy[5],  P[off[5]],  a1);
                    a2 = fmaf(wxy[6],  P[off[6]],  a2);
                    a3 = fmaf(wxy[7],  P[off[7]],  a3);
                    a0 = fmaf(wxy[8],  P[off[8]],  a0);
                    a1 = fmaf(wxy[9],  P[off[9]],  a1);
                    a2 = fmaf(wxy[10], P[off[10]], a2);
                    a3 = fmaf(wxy[11], P[off[11]], a3);
                    a0 = fmaf(wxy[12], P[off[12]], a0);
                    a1 = fmaf(wxy[13], P[off[13]], a1);
                    a2 = fmaf(wxy[14], P[off[14]], a2);
                    a3 = fmaf(wxy[15], P[off[15]], a3);
                    op[(c + 1) * NPOS] = (a0 + a1) + (a2 + a3);
                }
                __syncthreads();
            }
        }
    } else {
        // ---------------- fallback: direct gather (R8-proven) ----------------
        if (tid >= NPOS) return;
        int   off[16];
        float wxy[16];
        {
            int ry[4] = { y0a[0] * W, y1a[0] * W, y0a[1] * W, y1a[1] * W };
            int rx[4] = { x0a[0], x1a[0], x0a[1], x1a[1] };
            #pragma unroll
            for (int k = 0; k < 4; k++)
                #pragma unroll
                for (int l = 0; l < 4; l++) {
                    off[k * 4 + l] = ry[k] + rx[l];
                    wxy[k * 4 + l] = wy[k] * wx[l];
                }
        }
        const float* fp = fp0;
        #pragma unroll 1
        for (int c = 0; c < CHALF; c++) {
            float a0 = wxy[0]  * __ldg(fp + off[0]);
            float a1 = wxy[1]  * __ldg(fp + off[1]);
            float a2 = wxy[2]  * __ldg(fp + off[2]);
            float a3 = wxy[3]  * __ldg(fp + off[3]);
            a0 = fmaf(wxy[4],  __ldg(fp + off[4]),  a0);
            a1 = fmaf(wxy[5],  __ldg(fp + off[5]),  a1);
            a2 = fmaf(wxy[6],  __ldg(fp + off[6]),  a2);
            a3 = fmaf(wxy[7],  __ldg(fp + off[7]),  a3);
            a0 = fmaf(wxy[8],  __ldg(fp + off[8]),  a0);
            a1 = fmaf(wxy[9],  __ldg(fp + off[9]),  a1);
            a2 = fmaf(wxy[10], __ldg(fp + off[10]), a2);
            a3 = fmaf(wxy[11], __ldg(fp + off[11]), a3);
            a0 = fmaf(wxy[12], __ldg(fp + off[12]), a0);
            a1 = fmaf(wxy[13], __ldg(fp + off[13]), a1);
            a2 = fmaf(wxy[14], __ldg(fp + off[14]), a2);
            a3 = fmaf(wxy[15], __ldg(fp + off[15]), a3);
            op[c * NPOS] = (a0 + a1) + (a2 + a3);
            fp += HW;
        }
    }
}

extern "C" void kernel_launch(void* const* d_in, const int* in_sizes, int n_in,
                              void* d_out, int out_size)
{
    const float* p4     = (const float*)d_in[0];
    const float* p8     = (const float*)d_in[1];
    const float* p16    = (const float*)d_in[2];
    const float* p32    = (const float*)d_in[3];
    const float* boxes  = (const float*)d_in[4];
    const float* scores = (const float*)d_in[5];
    float* out = (float*)d_out;

    nms_kernel<<<BB, NN>>>(boxes, scores, out);
    pool_kernel<<<BB * NN * 2, 256>>>(p4, p8, p16, p32, out);
}

// round 11
// speedup vs baseline: 1.6294x; 1.4028x over previous
#include <cuda_runtime.h>
#include <math.h>

#define BB 2
#define NN 512
#define CC 256
#define OUTSZ 14
#define POOL_PER_BOX (CC * OUTSZ * OUTSZ)   // 50176
#define NPOS (OUTSZ * OUTSZ)                // 196
#define NMS_THRC 0.5f
#define CHALF (CC / 2)                      // 128 channels per pool block
#define PSZ 1024                            // patch floats per channel (true worst ~1008)
#define NCH 4                               // channels staged per phase
#define NPH (CHALF / NCH)                   // 32 phases

// Scratch (no allocations allowed)
__device__ float g_verts[BB * NN * 4];      // original order
__device__ int   g_level[BB * NN];          // original order
__device__ int   g_keep [BB * NN];          // original order

// ---------------------------------------------------------------------------
// Kernel 1: fully fused NMS. Grid = BB, 512 threads.
// rank-by-counting stable sort -> smem mask build (div-free IoU) -> ffs scan.
// ---------------------------------------------------------------------------
__global__ __launch_bounds__(NN) void nms_kernel(const float* __restrict__ boxes,
                                                 const float* __restrict__ scores,
                                                 float* __restrict__ out)
{
    const int b   = blockIdx.x;
    const int tid = threadIdx.x;

    __shared__ float         sscore[NN];
    __shared__ float4        sbox[NN];
    __shared__ float         sarea[NN];
    __shared__ unsigned char slev[NN];
    __shared__ short         sord[NN];
    __shared__ unsigned      smask[NN][16];
    __shared__ unsigned      keepw_s[16];

    const float* bbp = boxes + (size_t)b * NN * 4;
    float cx = bbp[tid * 4 + 0];
    float cy = bbp[tid * 4 + 1];
    float w  = bbp[tid * 4 + 2];
    float h  = bbp[tid * 4 + 3];
    float x1 = cx - w * 0.5f;
    float y1 = cy - h * 0.5f;
    float x2 = cx + w * 0.5f;
    float y2 = cy + h * 0.5f;

    float lv = floorf(3.0f + log2f(sqrtf(w * h) / 224.0f));
    lv = fminf(fmaxf(lv, 1.0f), 4.0f);
    int lev = (int)lv;

    int gi = b * NN + tid;
    g_verts[gi * 4 + 0] = x1;
    g_verts[gi * 4 + 1] = y1;
    g_verts[gi * 4 + 2] = x2;
    g_verts[gi * 4 + 3] = y2;
    g_level[gi] = lev;

    float ms = scores[gi];
    sscore[tid] = ms;
    __syncthreads();

    // stable descending rank by counting
    int r = 0;
    #pragma unroll 8
    for (int j = 0; j < NN; j++) {
        float sj = sscore[j];
        r += (sj > ms) || (sj == ms && j < tid);
    }

    sbox [r] = make_float4(x1, y1, x2, y2);
    sarea[r] = (x2 - x1) * (y2 - y1);
    slev [r] = (unsigned char)lev;
    sord [r] = (short)tid;
    __syncthreads();

    // suppression-matrix row for sorted rank tid (division-free IoU test:
    // inter/(den+eps) > 0.5  <=>  2*inter > den+eps, den >= 0)
    {
        float4 mb = sbox[tid];
        float  marea = sarea[tid];
        unsigned char mylev = slev[tid];
        const int myw = tid >> 5;
        for (int wq = 0; wq < myw; wq++) smask[tid][wq] = 0u;
        for (int wq = myw; wq < 16; wq++) {
            unsigned bits = 0u;
            #pragma unroll
            for (int jb = 0; jb < 32; jb++) {
                int j = (wq << 5) + jb;
                float4 ob = sbox[j];
                float ix1 = fmaxf(mb.x, ob.x);
                float iy1 = fmaxf(mb.y, ob.y);
                float ix2 = fminf(mb.z, ob.z);
                float iy2 = fminf(mb.w, ob.w);
                float iw = fmaxf(ix2 - ix1, 0.0f);
                float ih = fmaxf(iy2 - iy1, 0.0f);
                float inter = iw * ih;
                float den = marea + sarea[j] - inter + 1e-9f;
                bool sup = (j > tid) && (slev[j] == mylev) && (inter + inter > den * NMS_THRC * 2.0f * 0.5f + (den - den)) ;
                // simplified exact form: 2*inter > den  (thr = 0.5)
                sup = (j > tid) && (slev[j] == mylev) && (inter + inter > den);
                bits |= ((unsigned)sup) << jb;
            }
            smask[tid][wq] = bits;
        }
    }
    __syncthreads();

    // greedy scan: single warp, ffs-skip over kept boxes
    if (tid < 32) {
        int wl = tid & 15;
        unsigned kw = 0xFFFFFFFFu;
        for (int wq = 0; wq < 16; wq++) {
            unsigned cur = __shfl_sync(0xffffffffu, kw, wq);
            while (cur) {
                int bq = __ffs(cur) - 1;
                int row = (wq << 5) + bq;
                unsigned mw = smask[row][wl];
                unsigned mq = smask[row][wq];
                cur &= ~(mq | (1u << bq));
                kw  &= ~mw;
            }
        }
        if (tid < 16) keepw_s[tid] = kw;
    }
    __syncthreads();

    int kept = (keepw_s[tid >> 5] >> (tid & 31)) & 1;
    int o   = sord[tid];
    int go  = b * NN + o;
    g_keep[go] = kept;

    float4 sb = sbox[tid];
    float* ob = out + (size_t)BB * NN * POOL_PER_BOX;
    float* ok = ob + (size_t)BB * NN * 4;
    ob[go * 4 + 0] = kept ? sb.x : 0.0f;
    ob[go * 4 + 1] = kept ? sb.y : 0.0f;
    ob[go * 4 + 2] = kept ? sb.z : 0.0f;
    ob[go * 4 + 3] = kept ? sb.w : 0.0f;
    ok[go] = kept ? 1.0f : 0.0f;
}

// ---------------------------------------------------------------------------
// cp.async helpers
// ---------------------------------------------------------------------------
__device__ __forceinline__ void cpa4(unsigned dst_smem, const float* src) {
    asm volatile("cp.async.ca.shared.global [%0], [%1], 4;"
                 :: "r"(dst_smem), "l"(src) : "memory");
}
__device__ __forceinline__ void cpa_commit() {
    asm volatile("cp.async.commit_group;" ::: "memory");
}
__device__ __forceinline__ void cpa_wait1() {
    asm volatile("cp.async.wait_group 1;" ::: "memory");
}
__device__ __forceinline__ void cpa_wait0() {
    asm volatile("cp.async.wait_group 0;" ::: "memory");
}

// ---------------------------------------------------------------------------
// Kernel 2: ROI align via SMEM patch, 4 channels per phase, cp.async
// double-buffered. Two blocks per box (channel halves).
// ---------------------------------------------------------------------------
__global__ __launch_bounds__(256) void pool_kernel(const float* __restrict__ p4,
                                                   const float* __restrict__ p8,
                                                   const float* __restrict__ p16,
                                                   const float* __restrict__ p32,
                                                   float* __restrict__ out)
{
    const int bn   = blockIdx.x >> 1;
    const int half = blockIdx.x & 1;
    const int b    = bn / NN;
    const int tid  = threadIdx.x;

    float* o = out + (size_t)bn * POOL_PER_BOX + (size_t)half * CHALF * NPOS;

    if (!g_keep[bn]) {
        float4* o4 = (float4*)o;
        float4 z = make_float4(0.f, 0.f, 0.f, 0.f);
        #pragma unroll 4
        for (int i = tid; i < CHALF * NPOS / 4; i += 256) o4[i] = z;
        return;
    }

    const int lev = g_level[bn];
    const float* feat;
    int H;
    float stride;
    if (lev == 1)      { feat = p4;  H = 256; stride = 4.0f;  }
    else if (lev == 2) { feat = p8;  H = 128; stride = 8.0f;  }
    else if (lev == 3) { feat = p16; H = 64;  stride = 16.0f; }
    else               { feat = p32; H = 32;  stride = 32.0f; }
    const int W  = H;
    const int HW = H * W;

    float inv = 1.0f / stride;
    float rx1 = g_verts[bn * 4 + 0] * inv;
    float ry1 = g_verts[bn * 4 + 1] * inv;
    float rx2 = g_verts[bn * 4 + 2] * inv;
    float ry2 = g_verts[bn * 4 + 3] * inv;
    float bw = (rx2 - rx1) / (float)OUTSZ;
    float bh = (ry2 - ry1) / (float)OUTSZ;

    // Uniform patch bounds (samples monotone in index)
    float xsf = fminf(fmaxf(rx1 + 0.25f  * bw, 0.0f), (float)W - 1.0f);
    float xsl = fminf(fmaxf(rx1 + 13.75f * bw, 0.0f), (float)W - 1.0f);
    float ysf = fminf(fmaxf(ry1 + 0.25f  * bh, 0.0f), (float)H - 1.0f);
    float ysl = fminf(fmaxf(ry1 + 13.75f * bh, 0.0f), (float)H - 1.0f);
    const int xmin  = (int)floorf(xsf);
    const int xmax  = min((int)floorf(xsl) + 1, W - 1);
    const int ymin  = (int)floorf(ysf);
    const int ymax  = min((int)floorf(ysl) + 1, H - 1);
    const int pcols = xmax - xmin + 1;
    const int prows = ymax - ymin + 1;
    const int pp    = prows * pcols;

    // Per-thread sample data (absolute)
    const int oy = (tid < NPOS) ? (tid / OUTSZ) : 0;
    const int ox = (tid < NPOS) ? (tid - oy * OUTSZ) : 0;

    int   x0a[2], x1a[2];
    float wx[4];
    #pragma unroll
    for (int j = 0; j < 2; j++) {
        float g  = ((float)(2 * ox + j) + 0.5f) * 0.5f;
        float xs = fminf(fmaxf(rx1 + g * bw, 0.0f), (float)W - 1.0f);
        float x0f = floorf(xs);
        int   x0  = (int)x0f;
        float lx  = xs - x0f;
        x0a[j] = x0;
        x1a[j] = min(x0 + 1, W - 1);
        wx[2 * j]     = 1.0f - lx;
        wx[2 * j + 1] = lx;
    }
    int   y0a[2], y1a[2];
    float wy[4];
    #pragma unroll
    for (int j = 0; j < 2; j++) {
        float g  = ((float)(2 * oy + j) + 0.5f) * 0.5f;
        float ys = fminf(fmaxf(ry1 + g * bh, 0.0f), (float)H - 1.0f);
        float y0f = floorf(ys);
        int   y0  = (int)y0f;
        float ly  = ys - y0f;
        y0a[j] = y0;
        y1a[j] = min(y0 + 1, H - 1);
        wy[2 * j]     = 0.25f * (1.0f - ly);
        wy[2 * j + 1] = 0.25f * ly;
    }

    const float* fp0 = feat + ((size_t)b * CC + (size_t)half * CHALF) * HW;
    float* op = o + tid;

    if (pp <= PSZ) {
        // ---------------- SMEM patch path (4 ch/phase, cp.async) -----------
        __shared__ float patch[2][NCH * PSZ];

        int   off[16];
        float wxy[16];
        {
            int ry[4] = { (y0a[0] - ymin) * pcols, (y1a[0] - ymin) * pcols,
                          (y0a[1] - ymin) * pcols, (y1a[1] - ymin) * pcols };
            int rx[4] = { x0a[0] - xmin, x1a[0] - xmin,
                          x0a[1] - xmin, x1a[1] - xmin };
            #pragma unroll
            for (int k = 0; k < 4; k++)
                #pragma unroll
                for (int l = 0; l < 4; l++) {
                    off[k * 4 + l] = ry[k] + rx[l];
                    wxy[k * 4 + l] = wy[k] * wx[l];
                }
        }

        // per-channel staging plan (channel-invariant), up to 4 slots
        int so[4];
        #pragma unroll
        for (int s = 0; s < 4; s++) {
            int i = tid + s * 256;
            int py = i / pcols;
            int px = i - py * pcols;
            so[s] = py * W + px;
        }
        const int nslot = (pp - tid + 255) / 256;   // how many of my slots valid
        const float* fb = fp0 + (size_t)ymin * W + xmin;
        const unsigned spbase = (unsigned)__cvta_generic_to_shared(&patch[0][0]);

        // stage phase 0 into buf 0
        {
            #pragma unroll
            for (int ch = 0; ch < NCH; ch++) {
                const float* gch = fb + (size_t)ch * HW;
                unsigned dch = spbase + (unsigned)(ch * PSZ + tid) * 4u;
                #pragma unroll
                for (int s = 0; s < 4; s++)
                    if (s < nslot) cpa4(dch + s * 1024u, gch + so[s]);
            }
            cpa_commit();
        }

        int buf = 0;
        #pragma unroll 1
        for (int ph = 0; ph < NPH; ph++) {
            if (ph + 1 < NPH) {
                const float* fbn = fb + (size_t)(ph + 1) * NCH * HW;
                unsigned db = spbase + (unsigned)((buf ^ 1) * NCH * PSZ + tid) * 4u;
                #pragma unroll
                for (int ch = 0; ch < NCH; ch++) {
                    const float* gch = fbn + (size_t)ch * HW;
                    unsigned dch = db + (unsigned)(ch * PSZ) * 4u;
                    #pragma unroll
                    for (int s = 0; s < 4; s++)
                        if (s < nslot) cpa4(dch + s * 1024u, gch + so[s]);
                }
                cpa_commit();
                cpa_wait1();
            } else {
                cpa_wait0();
            }
            __syncthreads();

            if (tid < NPOS) {
                const float* P0 = &patch[buf][0];
                const float* P1 = P0 + PSZ;
                const float* P2 = P1 + PSZ;
                const float* P3 = P2 + PSZ;
                float a0 = 0.f, a1 = 0.f, a2 = 0.f, a3 = 0.f;
                #pragma unroll
                for (int k = 0; k < 16; k++) {
                    float wgt = wxy[k];
                    int   of  = off[k];
                    a0 = fmaf(wgt, P0[of], a0);
                    a1 = fmaf(wgt, P1[of], a1);
                    a2 = fmaf(wgt, P2[of], a2);
                    a3 = fmaf(wgt, P3[of], a3);
                }
                int c0 = ph * NCH;
                op[(c0 + 0) * NPOS] = a0;
                op[(c0 + 1) * NPOS] = a1;
                op[(c0 + 2) * NPOS] = a2;
                op[(c0 + 3) * NPOS] = a3;
            }
            __syncthreads();
            buf ^= 1;
        }
    } else {
        // ---------------- fallback: direct gather (should never trigger) ---
        if (tid >= NPOS) return;
        int   off[16];
        float wxy[16];
        {
            int ry[4] = { y0a[0] * W, y1a[0] * W, y0a[1] * W, y1a[1] * W };
            int rx[4] = { x0a[0], x1a[0], x0a[1], x1a[1] };
            #pragma unroll
            for (int k = 0; k < 4; k++)
                #pragma unroll
                for (int l = 0; l < 4; l++) {
                    off[k * 4 + l] = ry[k] + rx[l];
                    wxy[k * 4 + l] = wy[k] * wx[l];
                }
        }
        const float* fp = fp0;
        #pragma unroll 1
        for (int c = 0; c < CHALF; c++) {
            float a0 = wxy[0]  * __ldg(fp + off[0]);
            float a1 = wxy[1]  * __ldg(fp + off[1]);
            float a2 = wxy[2]  * __ldg(fp + off[2]);
            float a3 = wxy[3]  * __ldg(fp + off[3]);
            a0 = fmaf(wxy[4],  __ldg(fp + off[4]),  a0);
            a1 = fmaf(wxy[5],  __ldg(fp + off[5]),  a1);
            a2 = fmaf(wxy[6],  __ldg(fp + off[6]),  a2);
            a3 = fmaf(wxy[7],  __ldg(fp + off[7]),  a3);
            a0 = fmaf(wxy[8],  __ldg(fp + off[8]),  a0);
            a1 = fmaf(wxy[9],  __ldg(fp + off[9]),  a1);
            a2 = fmaf(wxy[10], __ldg(fp + off[10]), a2);
            a3 = fmaf(wxy[11], __ldg(fp + off[11]), a3);
            a0 = fmaf(wxy[12], __ldg(fp + off[12]), a0);
            a1 = fmaf(wxy[13], __ldg(fp + off[13]), a1);
            a2 = fmaf(wxy[14], __ldg(fp + off[14]), a2);
            a3 = fmaf(wxy[15], __ldg(fp + off[15]), a3);
            op[c * NPOS] = (a0 + a1) + (a2 + a3);
            fp += HW;
        }
    }
}

extern "C" void kernel_launch(void* const* d_in, const int* in_sizes, int n_in,
                              void* d_out, int out_size)
{
    const float* p4     = (const float*)d_in[0];
    const float* p8     = (const float*)d_in[1];
    const float* p16    = (const float*)d_in[2];
    const float* p32    = (const float*)d_in[3];
    const float* boxes  = (const float*)d_in[4];
    const float* scores = (const float*)d_in[5];
    float* out = (float*)d_out;

    nms_kernel<<<BB, NN>>>(boxes, scores, out);
    pool_kernel<<<BB * NN * 2, 256>>>(p4, p8, p16, p32, out);
}

// round 12
// speedup vs baseline: 1.7166x; 1.0535x over previous
#include <cuda_runtime.h>
#include <math.h>

#define BB 2
#define NN 512
#define CC 256
#define OUTSZ 14
#define POOL_PER_BOX (CC * OUTSZ * OUTSZ)   // 50176
#define NPOS (OUTSZ * OUTSZ)                // 196
#define CHALF (CC / 2)                      // 128 channels per pool block
#define PSZ 1280                            // patch floats per channel (worst ~1058)
#define NCH 4                               // channels staged per phase
#define NPH (CHALF / NCH)                   // 32 phases

// Scratch (no allocations allowed)
__device__ float  g_verts[BB * NN * 4];     // original order
__device__ int    g_level[BB * NN];         // original order
__device__ int    g_keep [BB * NN];         // original order
__device__ float4 gs_box [BB * NN];         // sorted order
__device__ float  gs_area[BB * NN];
__device__ int    gs_lev [BB * NN];
__device__ int    gs_ord [BB * NN];
__device__ uint4  g_mask [BB * NN];         // suppression matrix rows (4x uint4 = 16 words) -> use [BB*NN*4]
__device__ uint4  g_mask4[BB * NN * 4];

// ---------------------------------------------------------------------------
// Kernel A: verts + level + counting-rank stable sort. Grid=BB, 512 thr.
// ---------------------------------------------------------------------------
__global__ __launch_bounds__(NN) void nms_rank_kernel(const float* __restrict__ boxes,
                                                      const float* __restrict__ scores)
{
    const int b   = blockIdx.x;
    const int tid = threadIdx.x;

    __shared__ float sscore[NN];

    const float* bbp = boxes + (size_t)b * NN * 4;
    float cx = bbp[tid * 4 + 0];
    float cy = bbp[tid * 4 + 1];
    float w  = bbp[tid * 4 + 2];
    float h  = bbp[tid * 4 + 3];
    float x1 = cx - w * 0.5f;
    float y1 = cy - h * 0.5f;
    float x2 = cx + w * 0.5f;
    float y2 = cy + h * 0.5f;

    float lv = floorf(3.0f + log2f(sqrtf(w * h) / 224.0f));
    lv = fminf(fmaxf(lv, 1.0f), 4.0f);
    int lev = (int)lv;

    int gi = b * NN + tid;
    g_verts[gi * 4 + 0] = x1;
    g_verts[gi * 4 + 1] = y1;
    g_verts[gi * 4 + 2] = x2;
    g_verts[gi * 4 + 3] = y2;
    g_level[gi] = lev;

    float ms = scores[gi];
    sscore[tid] = ms;
    __syncthreads();

    int r = 0;
    #pragma unroll 8
    for (int j = 0; j < NN; j++) {
        float sj = sscore[j];
        r += (sj > ms) || (sj == ms && j < tid);
    }

    int gr = b * NN + r;
    gs_box [gr] = make_float4(x1, y1, x2, y2);
    gs_area[gr] = (x2 - x1) * (y2 - y1);
    gs_lev [gr] = lev;
    gs_ord [gr] = tid;
}

// ---------------------------------------------------------------------------
// Kernel B: suppression-matrix build. Grid = BB*8 x 64 threads.
// Thread owns row r = 8*tid + sub (interleaved => balanced upper-tri work).
// Division-free IoU test (thr = 0.5): 2*inter > den.
// ---------------------------------------------------------------------------
__global__ __launch_bounds__(64) void nms_mask_kernel()
{
    const int b   = blockIdx.x >> 3;
    const int sub = blockIdx.x & 7;
    const int tid = threadIdx.x;

    __shared__ float4        sbox[NN];
    __shared__ float         sarea[NN];
    __shared__ unsigned char slev[NN];

    for (int i = tid; i < NN; i += 64) {
        int g = b * NN + i;
        sbox[i]  = gs_box[g];
        sarea[i] = gs_area[g];
        slev[i]  = (unsigned char)gs_lev[g];
    }
    __syncthreads();

    const int r = tid * 8 + sub;
    float4 mb = sbox[r];
    float  marea = sarea[r];
    unsigned char mylev = slev[r];
    const int myw = r >> 5;

    unsigned mrow[16];
    for (int wq = 0; wq < myw; wq++) mrow[wq] = 0u;
    for (int wq = myw; wq < 16; wq++) {
        unsigned bits = 0u;
        #pragma unroll
        for (int jb = 0; jb < 32; jb++) {
            int j = (wq << 5) + jb;
            float4 ob = sbox[j];
            float ix1 = fmaxf(mb.x, ob.x);
            float iy1 = fmaxf(mb.y, ob.y);
            float ix2 = fminf(mb.z, ob.z);
            float iy2 = fminf(mb.w, ob.w);
            float iw = fmaxf(ix2 - ix1, 0.0f);
            float ih = fmaxf(iy2 - iy1, 0.0f);
            float inter = iw * ih;
            float den = marea + sarea[j] - inter + 1e-9f;
            bool sup = (j > r) && (slev[j] == mylev) && (inter + inter > den);
            bits |= ((unsigned)sup) << jb;
        }
        mrow[wq] = bits;
    }
    uint4* dst = &g_mask4[(size_t)(b * NN + r) * 4];
    dst[0] = make_uint4(mrow[0],  mrow[1],  mrow[2],  mrow[3]);
    dst[1] = make_uint4(mrow[4],  mrow[5],  mrow[6],  mrow[7]);
    dst[2] = make_uint4(mrow[8],  mrow[9],  mrow[10], mrow[11]);
    dst[3] = make_uint4(mrow[12], mrow[13], mrow[14], mrow[15]);
}

// ---------------------------------------------------------------------------
// Kernel C: greedy scan + keep/out_boxes/keep-flag writes. Grid=BB, 512 thr.
// ---------------------------------------------------------------------------
__global__ __launch_bounds__(NN) void nms_scan_kernel(float* __restrict__ out)
{
    const int b   = blockIdx.x;
    const int tid = threadIdx.x;

    __shared__ unsigned smask[NN][16];
    __shared__ unsigned keepw_s[16];

    {
        const uint4* src = &g_mask4[(size_t)b * NN * 4];
        uint4* dst = (uint4*)smask;
        #pragma unroll
        for (int i = tid; i < NN * 4; i += NN) dst[i] = src[i];
    }
    __syncthreads();

    if (tid < 32) {
        int wl = tid & 15;
        unsigned kw = 0xFFFFFFFFu;
        for (int wq = 0; wq < 16; wq++) {
            unsigned cur = __shfl_sync(0xffffffffu, kw, wq);
            while (cur) {
                int bq = __ffs(cur) - 1;
                int row = (wq << 5) + bq;
                unsigned mw = smask[row][wl];
                unsigned mq = smask[row][wq];
                cur &= ~(mq | (1u << bq));
                kw  &= ~mw;
            }
        }
        if (tid < 16) keepw_s[tid] = kw;
    }
    __syncthreads();

    int kept = (keepw_s[tid >> 5] >> (tid & 31)) & 1;
    int gr = b * NN + tid;
    int go = b * NN + gs_ord[gr];
    g_keep[go] = kept;

    float4 sb = gs_box[gr];
    float* ob = out + (size_t)BB * NN * POOL_PER_BOX;
    float* ok = ob + (size_t)BB * NN * 4;
    ob[go * 4 + 0] = kept ? sb.x : 0.0f;
    ob[go * 4 + 1] = kept ? sb.y : 0.0f;
    ob[go * 4 + 2] = kept ? sb.z : 0.0f;
    ob[go * 4 + 3] = kept ? sb.w : 0.0f;
    ok[go] = kept ? 1.0f : 0.0f;
}

// ---------------------------------------------------------------------------
// cp.async helpers
// ---------------------------------------------------------------------------
__device__ __forceinline__ void cpa4(unsigned dst_smem, const float* src) {
    asm volatile("cp.async.ca.shared.global [%0], [%1], 4;"
                 :: "r"(dst_smem), "l"(src) : "memory");
}
__device__ __forceinline__ void cpa_commit() {
    asm volatile("cp.async.commit_group;" ::: "memory");
}
__device__ __forceinline__ void cpa_wait0() {
    asm volatile("cp.async.wait_group 0;" ::: "memory");
}

// ---------------------------------------------------------------------------
// Kernel 2: ROI align via SMEM patch, 4 ch/phase, cp.async double-buffered,
// ONE sync per phase. Two blocks per box (channel halves). Register-lean.
// ---------------------------------------------------------------------------
__global__ __launch_bounds__(256, 4) void pool_kernel(const float* __restrict__ p4,
                                                      const float* __restrict__ p8,
                                                      const float* __restrict__ p16,
                                                      const float* __restrict__ p32,
                                                      float* __restrict__ out)
{
    const int bn   = blockIdx.x >> 1;
    const int half = blockIdx.x & 1;
    const int b    = bn / NN;
    const int tid  = threadIdx.x;

    float* o = out + (size_t)bn * POOL_PER_BOX + (size_t)half * CHALF * NPOS;

    if (!g_keep[bn]) {
        float4* o4 = (float4*)o;
        float4 z = make_float4(0.f, 0.f, 0.f, 0.f);
        #pragma unroll 4
        for (int i = tid; i < CHALF * NPOS / 4; i += 256) o4[i] = z;
        return;
    }

    const int lev = g_level[bn];
    const float* feat;
    int H;
    float stride;
    if (lev == 1)      { feat = p4;  H = 256; stride = 4.0f;  }
    else if (lev == 2) { feat = p8;  H = 128; stride = 8.0f;  }
    else if (lev == 3) { feat = p16; H = 64;  stride = 16.0f; }
    else               { feat = p32; H = 32;  stride = 32.0f; }
    const int W  = H;
    const int HW = H * W;

    float inv = 1.0f / stride;
    float rx1 = g_verts[bn * 4 + 0] * inv;
    float ry1 = g_verts[bn * 4 + 1] * inv;
    float rx2 = g_verts[bn * 4 + 2] * inv;
    float ry2 = g_verts[bn * 4 + 3] * inv;
    float bw = (rx2 - rx1) / (float)OUTSZ;
    float bh = (ry2 - ry1) / (float)OUTSZ;

    // Uniform patch bounds (samples monotone in index)
    float xsf = fminf(fmaxf(rx1 + 0.25f  * bw, 0.0f), (float)W - 1.0f);
    float xsl = fminf(fmaxf(rx1 + 13.75f * bw, 0.0f), (float)W - 1.0f);
    float ysf = fminf(fmaxf(ry1 + 0.25f  * bh, 0.0f), (float)H - 1.0f);
    float ysl = fminf(fmaxf(ry1 + 13.75f * bh, 0.0f), (float)H - 1.0f);
    const int xmin  = (int)floorf(xsf);
    const int xmax  = min((int)floorf(xsl) + 1, W - 1);
    const int ymin  = (int)floorf(ysf);
    const int ymax  = min((int)floorf(ysl) + 1, H - 1);
    const int pcols = xmax - xmin + 1;
    const int prows = ymax - ymin + 1;
    const int pp    = prows * pcols;

    // Per-thread sample tables (compact: 4 col idx, 4 row idx, 8 weights)
    const int oy = (tid < NPOS) ? (tid / OUTSZ) : 0;
    const int ox = (tid < NPOS) ? (tid - oy * OUTSZ) : 0;

    int   rxo[4];          // col offsets
    float wx[4];
    #pragma unroll
    for (int j = 0; j < 2; j++) {
        float g  = ((float)(2 * ox + j) + 0.5f) * 0.5f;
        float xs = fminf(fmaxf(rx1 + g * bw, 0.0f), (float)W - 1.0f);
        float x0f = floorf(xs);
        int   x0  = (int)x0f;
        float lx  = xs - x0f;
        rxo[2 * j]     = x0;
        rxo[2 * j + 1] = min(x0 + 1, W - 1);
        wx[2 * j]      = 1.0f - lx;
        wx[2 * j + 1]  = lx;
    }
    int   ryo[4];          // row indices (absolute)
    float wy[4];
    #pragma unroll
    for (int j = 0; j < 2; j++) {
        float g  = ((float)(2 * oy + j) + 0.5f) * 0.5f;
        float ys = fminf(fmaxf(ry1 + g * bh, 0.0f), (float)H - 1.0f);
        float y0f = floorf(ys);
        int   y0  = (int)y0f;
        float ly  = ys - y0f;
        ryo[2 * j]     = y0;
        ryo[2 * j + 1] = min(y0 + 1, H - 1);
        wy[2 * j]      = 0.25f * (1.0f - ly);
        wy[2 * j + 1]  = 0.25f * ly;
    }

    const float* fp0 = feat + ((size_t)b * CC + (size_t)half * CHALF) * HW;
    float* op = o + tid;

    if (pp <= PSZ) {
        // ---------------- SMEM patch path ----------------
        __shared__ float patch[2][NCH * PSZ];

        // make tables patch-relative
        #pragma unroll
        for (int k = 0; k < 4; k++) {
            rxo[k] -= xmin;
            ryo[k] = (ryo[k] - ymin) * pcols;
        }

        // staging plan (channel-invariant): up to 5 slots
        int so[5];
        #pragma unroll
        for (int s = 0; s < 5; s++) {
            int i = tid + s * 256;
            int py = i / pcols;
            int px = i - py * pcols;
            so[s] = py * W + px;
        }
        const int nslot = (pp > tid) ? ((pp - tid + 255) >> 8) : 0;
        const float* fb = fp0 + (size_t)ymin * W + xmin;
        const unsigned spbase = (unsigned)__cvta_generic_to_shared(&patch[0][0]);

        // prologue: stage phase 0 into buf 0
        #pragma unroll
        for (int ch = 0; ch < NCH; ch++) {
            const float* gch = fb + (size_t)ch * HW;
            unsigned dch = spbase + (unsigned)(ch * PSZ + tid) * 4u;
            #pragma unroll
            for (int s = 0; s < 5; s++)
                if (s < nslot) cpa4(dch + s * 1024u, gch + so[s]);
        }
        cpa_commit();

        #pragma unroll 1
        for (int ph = 0; ph < NPH; ph++) {
            const int buf = ph & 1;
            cpa_wait0();
            __syncthreads();      // buf data ready; everyone done with buf^1

            // prefetch next phase into buf^1 (safe: see sync above)
            if (ph + 1 < NPH) {
                const float* fbn = fb + (size_t)(ph + 1) * NCH * HW;
                unsigned db = spbase + (unsigned)((buf ^ 1) * NCH * PSZ + tid) * 4u;
                #pragma unroll
                for (int ch = 0; ch < NCH; ch++) {
                    const float* gch = fbn + (size_t)ch * HW;
                    unsigned dch = db + (unsigned)(ch * PSZ) * 4u;
                    #pragma unroll
                    for (int s = 0; s < 5; s++)
                        if (s < nslot) cpa4(dch + s * 1024u, gch + so[s]);
                }
                cpa_commit();
            }

            if (tid < NPOS) {
                const float* P0 = &patch[buf][0];
                const float* P1 = P0 + PSZ;
                const float* P2 = P1 + PSZ;
                const float* P3 = P2 + PSZ;
                float a0 = 0.f, a1 = 0.f, a2 = 0.f, a3 = 0.f;
                #pragma unroll
                for (int k = 0; k < 4; k++) {
                    int   ay  = ryo[k];
                    float wyk = wy[k];
                    #pragma unroll
                    for (int l = 0; l < 4; l++) {
                        float wgt = wyk * wx[l];
                        int   of  = ay + rxo[l];
                        a0 = fmaf(wgt, P0[of], a0);
                        a1 = fmaf(wgt, P1[of], a1);
                        a2 = fmaf(wgt, P2[of], a2);
                        a3 = fmaf(wgt, P3[of], a3);
                    }
                }
                int c0 = ph * NCH;
                op[(c0 + 0) * NPOS] = a0;
                op[(c0 + 1) * NPOS] = a1;
                op[(c0 + 2) * NPOS] = a2;
                op[(c0 + 3) * NPOS] = a3;
            }
        }
    } else {
        // ---------------- fallback: direct gather ----------------
        if (tid >= NPOS) return;
        const float* fp = fp0;
        #pragma unroll 1
        for (int c = 0; c < CHALF; c++) {
            float acc = 0.f;
            #pragma unroll
            for (int k = 0; k < 4; k++) {
                int   ay  = ryo[k] * W;
                float wyk = wy[k];
                #pragma unroll
                for (int l = 0; l < 4; l++)
                    acc = fmaf(wyk * wx[l], __ldg(fp + ay + rxo[l]), acc);
            }
            op[c * NPOS] = acc;
            fp += HW;
        }
    }
}

extern "C" void kernel_launch(void* const* d_in, const int* in_sizes, int n_in,
                              void* d_out, int out_size)
{
    const float* p4     = (const float*)d_in[0];
    const float* p8     = (const float*)d_in[1];
    const float* p16    = (const float*)d_in[2];
    const float* p32    = (const float*)d_in[3];
    const float* boxes  = (const float*)d_in[4];
    const float* scores = (const float*)d_in[5];
    float* out = (float*)d_out;

    nms_rank_kernel<<<BB, NN>>>(boxes, scores);
    nms_mask_kernel<<<BB * 8, 64>>>();
    nms_scan_kernel<<<BB, NN>>>(out);
    pool_kernel<<<BB * NN * 2, 256>>>(p4, p8, p16, p32, out);
}

// round 13
// speedup vs baseline: 1.9009x; 1.1074x over previous
#include <cuda_runtime.h>
#include <math.h>

#define BB 2
#define NN 512
#define CC 256
#define OUTSZ 14
#define POOL_PER_BOX (CC * OUTSZ * OUTSZ)   // 50176
#define NPOS (OUTSZ * OUTSZ)                // 196
#define CQ 64                               // channels per pool block (4-way split)
#define NCH 4                               // channels per phase (float4 interleave)
#define NPH (CQ / NCH)                      // 16 phases
#define PSZ 1024                            // patch elems per channel (worst ~991)

// Scratch (no allocations allowed)
__device__ float  g_verts[BB * NN * 4];     // original order
__device__ int    g_level[BB * NN];         // original order
__device__ int    g_keep [BB * NN];         // original order
__device__ int    gs_ord [BB * NN];         // sorted rank -> original index
__device__ uint4  g_mask4[BB * NN * 4];     // suppression matrix rows (sorted)

// ---------------------------------------------------------------------------
// Kernel M: rank (recomputed per block) + suppression-matrix build.
// Grid = BB*4, 128 threads. Block handles 128 interleaved sorted rows.
// ---------------------------------------------------------------------------
__global__ __launch_bounds__(128) void nms_mask_kernel(const float* __restrict__ boxes,
                                                       const float* __restrict__ scores)
{
    const int b   = blockIdx.x >> 2;
    const int sub = blockIdx.x & 3;
    const int tid = threadIdx.x;

    __shared__ float         sscore[NN];
    __shared__ float4        sbox[NN];
    __shared__ float         sarea[NN];
    __shared__ unsigned char slev[NN];

    // load scores
    #pragma unroll
    for (int q = 0; q < 4; q++) {
        int i = tid + q * 128;
        sscore[i] = scores[b * NN + i];
    }
    __syncthreads();

    // per-original: verts/level/rank; scatter into sorted smem arrays
    const float* bbp = boxes + (size_t)b * NN * 4;
    #pragma unroll
    for (int q = 0; q < 4; q++) {
        int i = tid + q * 128;
        float cx = bbp[i * 4 + 0];
        float cy = bbp[i * 4 + 1];
        float w  = bbp[i * 4 + 2];
        float h  = bbp[i * 4 + 3];
        float x1 = cx - w * 0.5f;
        float y1 = cy - h * 0.5f;
        float x2 = cx + w * 0.5f;
        float y2 = cy + h * 0.5f;
        float lv = floorf(3.0f + log2f(sqrtf(w * h) / 224.0f));
        lv = fminf(fmaxf(lv, 1.0f), 4.0f);
        int lev = (int)lv;

        float ms = sscore[i];
        int r = 0;
        #pragma unroll 8
        for (int j = 0; j < NN; j++) {
            float sj = sscore[j];
            r += (sj > ms) || (sj == ms && j < i);
        }

        sbox [r] = make_float4(x1, y1, x2, y2);
        sarea[r] = (x2 - x1) * (y2 - y1);
        slev [r] = (unsigned char)lev;

        if (sub == 0) {
            int gi = b * NN + i;
            g_verts[gi * 4 + 0] = x1;
            g_verts[gi * 4 + 1] = y1;
            g_verts[gi * 4 + 2] = x2;
            g_verts[gi * 4 + 3] = y2;
            g_level[gi] = lev;
            gs_ord[b * NN + r] = i;
        }
    }
    __syncthreads();

    // mask row r = tid*4 + sub (interleaved => balanced upper-tri work)
    const int r = tid * 4 + sub;
    float4 mb = sbox[r];
    float  marea = sarea[r];
    unsigned char mylev = slev[r];
    const int myw = r >> 5;

    unsigned mrow[16];
    for (int wq = 0; wq < myw; wq++) mrow[wq] = 0u;
    for (int wq = myw; wq < 16; wq++) {
        unsigned bits = 0u;
        #pragma unroll
        for (int jb = 0; jb < 32; jb++) {
            int j = (wq << 5) + jb;
            float4 ob = sbox[j];
            float ix1 = fmaxf(mb.x, ob.x);
            float iy1 = fmaxf(mb.y, ob.y);
            float ix2 = fminf(mb.z, ob.z);
            float iy2 = fminf(mb.w, ob.w);
            float iw = fmaxf(ix2 - ix1, 0.0f);
            float ih = fmaxf(iy2 - iy1, 0.0f);
            float inter = iw * ih;
            float den = marea + sarea[j] - inter + 1e-9f;     // IoU>0.5 <=> 2*inter>den
            bool sup = (j > r) && (slev[j] == mylev) && (inter + inter > den);
            bits |= ((unsigned)sup) << jb;
        }
        mrow[wq] = bits;
    }
    uint4* dst = &g_mask4[(size_t)(b * NN + r) * 4];
    dst[0] = make_uint4(mrow[0],  mrow[1],  mrow[2],  mrow[3]);
    dst[1] = make_uint4(mrow[4],  mrow[5],  mrow[6],  mrow[7]);
    dst[2] = make_uint4(mrow[8],  mrow[9],  mrow[10], mrow[11]);
    dst[3] = make_uint4(mrow[12], mrow[13], mrow[14], mrow[15]);
}

// ---------------------------------------------------------------------------
// Kernel S: greedy scan + keep/out_boxes/keep-flag writes. Grid=BB, 512 thr.
// ---------------------------------------------------------------------------
__global__ __launch_bounds__(NN) void nms_scan_kernel(float* __restrict__ out)
{
    const int b   = blockIdx.x;
    const int tid = threadIdx.x;

    __shared__ unsigned smask[NN][16];
    __shared__ unsigned keepw_s[16];

    {
        const uint4* src = &g_mask4[(size_t)b * NN * 4];
        uint4* dst = (uint4*)smask;
        #pragma unroll
        for (int i = tid; i < NN * 4; i += NN) dst[i] = src[i];
    }
    __syncthreads();

    if (tid < 32) {
        int wl = tid & 15;
        unsigned kw = 0xFFFFFFFFu;
        for (int wq = 0; wq < 16; wq++) {
            unsigned cur = __shfl_sync(0xffffffffu, kw, wq);
            while (cur) {
                int bq = __ffs(cur) - 1;
                int row = (wq << 5) + bq;
                unsigned mw = smask[row][wl];
                unsigned mq = smask[row][wq];
                cur &= ~(mq | (1u << bq));
                kw  &= ~mw;
            }
        }
        if (tid < 16) keepw_s[tid] = kw;
    }
    __syncthreads();

    int kept = (keepw_s[tid >> 5] >> (tid & 31)) & 1;
    int go = b * NN + gs_ord[b * NN + tid];
    g_keep[go] = kept;

    float* ob = out + (size_t)BB * NN * POOL_PER_BOX;
    float* ok = ob + (size_t)BB * NN * 4;
    ob[go * 4 + 0] = kept ? g_verts[go * 4 + 0] : 0.0f;
    ob[go * 4 + 1] = kept ? g_verts[go * 4 + 1] : 0.0f;
    ob[go * 4 + 2] = kept ? g_verts[go * 4 + 2] : 0.0f;
    ob[go * 4 + 3] = kept ? g_verts[go * 4 + 3] : 0.0f;
    ok[go] = kept ? 1.0f : 0.0f;
}

// ---------------------------------------------------------------------------
// cp.async helpers
// ---------------------------------------------------------------------------
__device__ __forceinline__ void cpa4(unsigned dst_smem, const float* src) {
    asm volatile("cp.async.ca.shared.global [%0], [%1], 4;"
                 :: "r"(dst_smem), "l"(src) : "memory");
}
__device__ __forceinline__ void cpa_commit() {
    asm volatile("cp.async.commit_group;" ::: "memory");
}
__device__ __forceinline__ void cpa_wait0() {
    asm volatile("cp.async.wait_group 0;" ::: "memory");
}

// ---------------------------------------------------------------------------
// Kernel P: ROI align. Patch channel-interleaved as float4 (4 channels per
// index) -> each tap is one LDS.128 serving 4 channels. 4 blocks per box
// (64 channels each), double-buffered cp.async, one sync per phase.
// ---------------------------------------------------------------------------
__global__ __launch_bounds__(256, 4) void pool_kernel(const float* __restrict__ p4,
                                                      const float* __restrict__ p8,
                                                      const float* __restrict__ p16,
                                                      const float* __restrict__ p32,
                                                      float* __restrict__ out)
{
    const int bn      = blockIdx.x >> 2;
    const int quarter = blockIdx.x & 3;
    const int b       = bn / NN;
    const int tid     = threadIdx.x;

    float* o = out + (size_t)bn * POOL_PER_BOX + (size_t)quarter * CQ * NPOS;

    if (!g_keep[bn]) {
        float4* o4 = (float4*)o;
        float4 z = make_float4(0.f, 0.f, 0.f, 0.f);
        #pragma unroll 4
        for (int i = tid; i < CQ * NPOS / 4; i += 256) o4[i] = z;
        return;
    }

    const int lev = g_level[bn];
    const float* feat;
    int H;
    float stride;
    if (lev == 1)      { feat = p4;  H = 256; stride = 4.0f;  }
    else if (lev == 2) { feat = p8;  H = 128; stride = 8.0f;  }
    else if (lev == 3) { feat = p16; H = 64;  stride = 16.0f; }
    else               { feat = p32; H = 32;  stride = 32.0f; }
    const int W  = H;
    const int HW = H * W;

    float inv = 1.0f / stride;
    float rx1 = g_verts[bn * 4 + 0] * inv;
    float ry1 = g_verts[bn * 4 + 1] * inv;
    float rx2 = g_verts[bn * 4 + 2] * inv;
    float ry2 = g_verts[bn * 4 + 3] * inv;
    float bw = (rx2 - rx1) / (float)OUTSZ;
    float bh = (ry2 - ry1) / (float)OUTSZ;

    // Uniform patch bounds (samples monotone in index)
    float xsf = fminf(fmaxf(rx1 + 0.25f  * bw, 0.0f), (float)W - 1.0f);
    float xsl = fminf(fmaxf(rx1 + 13.75f * bw, 0.0f), (float)W - 1.0f);
    float ysf = fminf(fmaxf(ry1 + 0.25f  * bh, 0.0f), (float)H - 1.0f);
    float ysl = fminf(fmaxf(ry1 + 13.75f * bh, 0.0f), (float)H - 1.0f);
    const int xmin  = (int)floorf(xsf);
    const int xmax  = min((int)floorf(xsl) + 1, W - 1);
    const int ymin  = (int)floorf(ysf);
    const int ymax  = min((int)floorf(ysl) + 1, H - 1);
    const int pcols = xmax - xmin + 1;
    const int prows = ymax - ymin + 1;
    const int pp    = prows * pcols;

    // Per-thread sample tables
    const int oy = (tid < NPOS) ? (tid / OUTSZ) : 0;
    const int ox = (tid < NPOS) ? (tid - oy * OUTSZ) : 0;

    int   rxo[4];
    float wx[4];
    #pragma unroll
    for (int j = 0; j < 2; j++) {
        float g  = ((float)(2 * ox + j) + 0.5f) * 0.5f;
        float xs = fminf(fmaxf(rx1 + g * bw, 0.0f), (float)W - 1.0f);
        float x0f = floorf(xs);
        int   x0  = (int)x0f;
        float lx  = xs - x0f;
        rxo[2 * j]     = x0;
        rxo[2 * j + 1] = min(x0 + 1, W - 1);
        wx[2 * j]      = 1.0f - lx;
        wx[2 * j + 1]  = lx;
    }
    int   ryo[4];
    float wy[4];
    #pragma unroll
    for (int j = 0; j < 2; j++) {
        float g  = ((float)(2 * oy + j) + 0.5f) * 0.5f;
        float ys = fminf(fmaxf(ry1 + g * bh, 0.0f), (float)H - 1.0f);
        float y0f = floorf(ys);
        int   y0  = (int)y0f;
        float ly  = ys - y0f;
        ryo[2 * j]     = y0;
        ryo[2 * j + 1] = min(y0 + 1, H - 1);
        wy[2 * j]      = 0.25f * (1.0f - ly);
        wy[2 * j + 1]  = 0.25f * ly;
    }

    const float* fp0 = feat + ((size_t)b * CC + (size_t)quarter * CQ) * HW;
    float* op = o + tid;

    if (pp <= PSZ) {
        // ---------------- interleaved SMEM patch path ----------------
        __shared__ float4 patch[2][PSZ];

        // patch-relative tables
        #pragma unroll
        for (int k = 0; k < 4; k++) {
            rxo[k] -= xmin;
            ryo[k] = (ryo[k] - ymin) * pcols;
        }

        // staging plan (channel-invariant): up to 4 slots
        int so[4];
        #pragma unroll
        for (int s = 0; s < 4; s++) {
            int i = tid + s * 256;
            int py = i / pcols;
            int px = i - py * pcols;
            so[s] = py * W + px;
        }
        const int nslot = (pp > tid) ? ((pp - tid + 255) >> 8) : 0;
        const float* fb = fp0 + (size_t)ymin * W + xmin;
        const unsigned spbase = (unsigned)__cvta_generic_to_shared(&patch[0][0]);

        // prologue: stage phase 0 into buf 0
        #pragma unroll
        for (int ch = 0; ch < NCH; ch++) {
            const float* gch = fb + (size_t)ch * HW;
            #pragma unroll
            for (int s = 0; s < 4; s++)
                if (s < nslot)
                    cpa4(spbase + (unsigned)(tid + s * 256) * 16u + ch * 4u, gch + so[s]);
        }
        cpa_commit();

        #pragma unroll 1
        for (int ph = 0; ph < NPH; ph++) {
            const int buf = ph & 1;
            cpa_wait0();
            __syncthreads();      // buf data ready; everyone done with buf^1

            if (ph + 1 < NPH) {
                const float* fbn = fb + (size_t)(ph + 1) * NCH * HW;
                unsigned db = spbase + (unsigned)(buf ^ 1) * (PSZ * 16u);
                #pragma unroll
                for (int ch = 0; ch < NCH; ch++) {
                    const float* gch = fbn + (size_t)ch * HW;
                    #pragma unroll
                    for (int s = 0; s < 4; s++)
                        if (s < nslot)
                            cpa4(db + (unsigned)(tid + s * 256) * 16u + ch * 4u, gch + so[s]);
                }
                cpa_commit();
            }

            if (tid < NPOS) {
                const float4* P = &patch[buf][0];
                float a0 = 0.f, a1 = 0.f, a2 = 0.f, a3 = 0.f;
                #pragma unroll
                for (int k = 0; k < 4; k++) {
                    int   ay  = ryo[k];
                    float wyk = wy[k];
                    #pragma unroll
                    for (int l = 0; l < 4; l++) {
                        float wgt = wyk * wx[l];
                        float4 v  = P[ay + rxo[l]];
                        a0 = fmaf(wgt, v.x, a0);
                        a1 = fmaf(wgt, v.y, a1);
                        a2 = fmaf(wgt, v.z, a2);
                        a3 = fmaf(wgt, v.w, a3);
                    }
                }
                int c0 = ph * NCH;
                op[(c0 + 0) * NPOS] = a0;
                op[(c0 + 1) * NPOS] = a1;
                op[(c0 + 2) * NPOS] = a2;
                op[(c0 + 3) * NPOS] = a3;
            }
        }
    } else {
        // ---------------- fallback: direct gather ----------------
        if (tid >= NPOS) return;
        const float* fp = fp0;
        #pragma unroll 1
        for (int c = 0; c < CQ; c++) {
            float acc = 0.f;
            #pragma unroll
            for (int k = 0; k < 4; k++) {
                int   ay  = ryo[k] * W;
                float wyk = wy[k];
                #pragma unroll
                for (int l = 0; l < 4; l++)
                    acc = fmaf(wyk * wx[l], __ldg(fp + ay + rxo[l]), acc);
            }
            op[c * NPOS] = acc;
            fp += HW;
        }
    }
}

extern "C" void kernel_launch(void* const* d_in, const int* in_sizes, int n_in,
                              void* d_out, int out_size)
{
    const float* p4     = (const float*)d_in[0];
    const float* p8     = (const float*)d_in[1];
    const float* p16    = (const float*)d_in[2];
    const float* p32    = (const float*)d_in[3];
    const float* boxes  = (const float*)d_in[4];
    const float* scores = (const float*)d_in[5];
    float* out = (float*)d_out;

    nms_mask_kernel<<<BB * 4, 128>>>(boxes, scores);
    nms_scan_kernel<<<BB, NN>>>(out);
    pool_kernel<<<BB * NN * 4, 256>>>(p4, p8, p16, p32, out);
}

// round 14
// speedup vs baseline: 2.2941x; 1.2068x over previous
#include <cuda_runtime.h>
#include <math.h>

#define BB 2
#define NN 512
#define CC 256
#define OUTSZ 14
#define POOL_PER_BOX (CC * OUTSZ * OUTSZ)   // 50176
#define NPOS (OUTSZ * OUTSZ)                // 196
#define CQ 64                               // channels per pool block (4-way split)
#define NCH 4                               // channels per phase (float4 interleave)
#define NPH (CQ / NCH)                      // 16 phases
#define PSZ 1024                            // patch elems per channel (worst ~991)

// Scratch (no allocations allowed)
__device__ float    g_verts[BB * NN * 4];   // original order
__device__ int      g_level[BB * NN];       // original order
__device__ int      g_keep [BB * NN];       // original order
__device__ float4   gs_box [BB * NN];       // sorted order
__device__ float    gs_area[BB * NN];
__device__ int      gs_lev [BB * NN];
__device__ int      gs_ord [BB * NN];       // sorted rank -> original index
__device__ unsigned g_maskw[BB * NN * 16];  // suppression matrix (sorted order)

// ---------------------------------------------------------------------------
// Kernel R: verts + level + counting-rank stable sort. Grid=BB, 512 thr.
// ---------------------------------------------------------------------------
__global__ __launch_bounds__(NN) void nms_rank_kernel(const float* __restrict__ boxes,
                                                      const float* __restrict__ scores)
{
    const int b   = blockIdx.x;
    const int tid = threadIdx.x;

    __shared__ float sscore[NN];

    const float* bbp = boxes + (size_t)b * NN * 4;
    float cx = bbp[tid * 4 + 0];
    float cy = bbp[tid * 4 + 1];
    float w  = bbp[tid * 4 + 2];
    float h  = bbp[tid * 4 + 3];
    float x1 = cx - w * 0.5f;
    float y1 = cy - h * 0.5f;
    float x2 = cx + w * 0.5f;
    float y2 = cy + h * 0.5f;

    float lv = floorf(3.0f + log2f(sqrtf(w * h) / 224.0f));
    lv = fminf(fmaxf(lv, 1.0f), 4.0f);
    int lev = (int)lv;

    int gi = b * NN + tid;
    g_verts[gi * 4 + 0] = x1;
    g_verts[gi * 4 + 1] = y1;
    g_verts[gi * 4 + 2] = x2;
    g_verts[gi * 4 + 3] = y2;
    g_level[gi] = lev;

    float ms = scores[gi];
    sscore[tid] = ms;
    __syncthreads();

    int r = 0;
    #pragma unroll 8
    for (int j = 0; j < NN; j++) {
        float sj = sscore[j];
        r += (sj > ms) || (sj == ms && j < tid);
    }

    int gr = b * NN + r;
    gs_box [gr] = make_float4(x1, y1, x2, y2);
    gs_area[gr] = (x2 - x1) * (y2 - y1);
    gs_lev [gr] = lev;
    gs_ord [gr] = tid;
}

// ---------------------------------------------------------------------------
// Kernel M: suppression-matrix build, WARP PER ROW via ballot.
// Grid = BB*64 blocks x 256 threads (8 warps = 8 rows per block).
// Lane l computes the predicate for column j = wq*32+l; ballot = mask word.
// Division-free IoU (thr = 0.5): 2*inter > den.
// ---------------------------------------------------------------------------
__global__ __launch_bounds__(256) void nms_mask_kernel()
{
    const int blk  = blockIdx.x;
    const int b    = blk >> 6;              // 64 blocks per batch
    const int rb   = (blk & 63) << 3;       // row base (8 rows per block)
    const int tid  = threadIdx.x;
    const int wid  = tid >> 5;
    const int lane = tid & 31;

    __shared__ float4        sbox[NN];
    __shared__ float         sarea[NN];
    __shared__ unsigned char slev[NN];

    #pragma unroll
    for (int q = 0; q < 2; q++) {
        int i = tid + q * 256;
        int g = b * NN + i;
        sbox[i]  = gs_box[g];
        sarea[i] = gs_area[g];
        slev[i]  = (unsigned char)gs_lev[g];
    }
    __syncthreads();

    const int r = rb + wid;
    float4 mb = sbox[r];
    float  marea = sarea[r];
    unsigned char mylev = slev[r];

    unsigned myword = 0u;
    #pragma unroll
    for (int wq = 0; wq < 16; wq++) {
        int j = (wq << 5) + lane;
        float4 ob = sbox[j];
        float ix1 = fmaxf(mb.x, ob.x);
        float iy1 = fmaxf(mb.y, ob.y);
        float ix2 = fminf(mb.z, ob.z);
        float iy2 = fminf(mb.w, ob.w);
        float iw = fmaxf(ix2 - ix1, 0.0f);
        float ih = fmaxf(iy2 - iy1, 0.0f);
        float inter = iw * ih;
        float den = marea + sarea[j] - inter + 1e-9f;
        bool sup = (j > r) && (slev[j] == mylev) && (inter + inter > den);
        unsigned word = __ballot_sync(0xffffffffu, sup);
        if (lane == wq) myword = word;
    }
    if (lane < 16)
        g_maskw[(size_t)(b * NN + r) * 16 + lane] = myword;
}

// ---------------------------------------------------------------------------
// Kernel S: greedy scan + keep/out_boxes/keep-flag writes. Grid=BB, 512 thr.
// ---------------------------------------------------------------------------
__global__ __launch_bounds__(NN) void nms_scan_kernel(float* __restrict__ out)
{
    const int b   = blockIdx.x;
    const int tid = threadIdx.x;

    __shared__ unsigned smask[NN][16];
    __shared__ unsigned keepw_s[16];

    {
        const uint4* src = (const uint4*)&g_maskw[(size_t)b * NN * 16];
        uint4* dst = (uint4*)smask;
        #pragma unroll
        for (int i = tid; i < NN * 4; i += NN) dst[i] = src[i];
    }
    __syncthreads();

    if (tid < 32) {
        int wl = tid & 15;
        unsigned kw = 0xFFFFFFFFu;
        for (int wq = 0; wq < 16; wq++) {
            unsigned cur = __shfl_sync(0xffffffffu, kw, wq);
            while (cur) {
                int bq = __ffs(cur) - 1;
                int row = (wq << 5) + bq;
                unsigned mw = smask[row][wl];
                unsigned mq = smask[row][wq];
                cur &= ~(mq | (1u << bq));
                kw  &= ~mw;
            }
        }
        if (tid < 16) keepw_s[tid] = kw;
    }
    __syncthreads();

    int kept = (keepw_s[tid >> 5] >> (tid & 31)) & 1;
    int go = b * NN + gs_ord[b * NN + tid];
    g_keep[go] = kept;

    float* ob = out + (size_t)BB * NN * POOL_PER_BOX;
    float* ok = ob + (size_t)BB * NN * 4;
    ob[go * 4 + 0] = kept ? g_verts[go * 4 + 0] : 0.0f;
    ob[go * 4 + 1] = kept ? g_verts[go * 4 + 1] : 0.0f;
    ob[go * 4 + 2] = kept ? g_verts[go * 4 + 2] : 0.0f;
    ob[go * 4 + 3] = kept ? g_verts[go * 4 + 3] : 0.0f;
    ok[go] = kept ? 1.0f : 0.0f;
}

// ---------------------------------------------------------------------------
// cp.async helpers
// ---------------------------------------------------------------------------
__device__ __forceinline__ void cpa4(unsigned dst_smem, const float* src) {
    asm volatile("cp.async.ca.shared.global [%0], [%1], 4;"
                 :: "r"(dst_smem), "l"(src) : "memory");
}
__device__ __forceinline__ void cpa_commit() {
    asm volatile("cp.async.commit_group;" ::: "memory");
}
__device__ __forceinline__ void cpa_wait0() {
    asm volatile("cp.async.wait_group 0;" ::: "memory");
}

// ---------------------------------------------------------------------------
// Kernel P: ROI align. Patch channel-interleaved as float4 (4 channels per
// index) -> each tap is one LDS.128 serving 4 channels. 4 blocks per box
// (64 channels each), double-buffered cp.async, one sync per phase.
// (Unchanged from R13 — proven.)
// ---------------------------------------------------------------------------
__global__ __launch_bounds__(256, 4) void pool_kernel(const float* __restrict__ p4,
                                                      const float* __restrict__ p8,
                                                      const float* __restrict__ p16,
                                                      const float* __restrict__ p32,
                                                      float* __restrict__ out)
{
    const int bn      = blockIdx.x >> 2;
    const int quarter = blockIdx.x & 3;
    const int b       = bn / NN;
    const int tid     = threadIdx.x;

    float* o = out + (size_t)bn * POOL_PER_BOX + (size_t)quarter * CQ * NPOS;

    if (!g_keep[bn]) {
        float4* o4 = (float4*)o;
        float4 z = make_float4(0.f, 0.f, 0.f, 0.f);
        #pragma unroll 4
        for (int i = tid; i < CQ * NPOS / 4; i += 256) o4[i] = z;
        return;
    }

    const int lev = g_level[bn];
    const float* feat;
    int H;
    float stride;
    if (lev == 1)      { feat = p4;  H = 256; stride = 4.0f;  }
    else if (lev == 2) { feat = p8;  H = 128; stride = 8.0f;  }
    else if (lev == 3) { feat = p16; H = 64;  stride = 16.0f; }
    else               { feat = p32; H = 32;  stride = 32.0f; }
    const int W  = H;
    const int HW = H * W;

    float inv = 1.0f / stride;
    float rx1 = g_verts[bn * 4 + 0] * inv;
    float ry1 = g_verts[bn * 4 + 1] * inv;
    float rx2 = g_verts[bn * 4 + 2] * inv;
    float ry2 = g_verts[bn * 4 + 3] * inv;
    float bw = (rx2 - rx1) / (float)OUTSZ;
    float bh = (ry2 - ry1) / (float)OUTSZ;

    float xsf = fminf(fmaxf(rx1 + 0.25f  * bw, 0.0f), (float)W - 1.0f);
    float xsl = fminf(fmaxf(rx1 + 13.75f * bw, 0.0f), (float)W - 1.0f);
    float ysf = fminf(fmaxf(ry1 + 0.25f  * bh, 0.0f), (float)H - 1.0f);
    float ysl = fminf(fmaxf(ry1 + 13.75f * bh, 0.0f), (float)H - 1.0f);
    const int xmin  = (int)floorf(xsf);
    const int xmax  = min((int)floorf(xsl) + 1, W - 1);
    const int ymin  = (int)floorf(ysf);
    const int ymax  = min((int)floorf(ysl) + 1, H - 1);
    const int pcols = xmax - xmin + 1;
    const int prows = ymax - ymin + 1;
    const int pp    = prows * pcols;

    const int oy = (tid < NPOS) ? (tid / OUTSZ) : 0;
    const int ox = (tid < NPOS) ? (tid - oy * OUTSZ) : 0;

    int   rxo[4];
    float wx[4];
    #pragma unroll
    for (int j = 0; j < 2; j++) {
        float g  = ((float)(2 * ox + j) + 0.5f) * 0.5f;
        float xs = fminf(fmaxf(rx1 + g * bw, 0.0f), (float)W - 1.0f);
        float x0f = floorf(xs);
        int   x0  = (int)x0f;
        float lx  = xs - x0f;
        rxo[2 * j]     = x0;
        rxo[2 * j + 1] = min(x0 + 1, W - 1);
        wx[2 * j]      = 1.0f - lx;
        wx[2 * j + 1]  = lx;
    }
    int   ryo[4];
    float wy[4];
    #pragma unroll
    for (int j = 0; j < 2; j++) {
        float g  = ((float)(2 * oy + j) + 0.5f) * 0.5f;
        float ys = fminf(fmaxf(ry1 + g * bh, 0.0f), (float)H - 1.0f);
        float y0f = floorf(ys);
        int   y0  = (int)y0f;
        float ly  = ys - y0f;
        ryo[2 * j]     = y0;
        ryo[2 * j + 1] = min(y0 + 1, H - 1);
        wy[2 * j]      = 0.25f * (1.0f - ly);
        wy[2 * j + 1]  = 0.25f * ly;
    }

    const float* fp0 = feat + ((size_t)b * CC + (size_t)quarter * CQ) * HW;
    float* op = o + tid;

    if (pp <= PSZ) {
        __shared__ float4 patch[2][PSZ];

        #pragma unroll
        for (int k = 0; k < 4; k++) {
            rxo[k] -= xmin;
            ryo[k] = (ryo[k] - ymin) * pcols;
        }

        int so[4];
        #pragma unroll
        for (int s = 0; s < 4; s++) {
            int i = tid + s * 256;
            int py = i / pcols;
            int px = i - py * pcols;
            so[s] = py * W + px;
        }
        const int nslot = (pp > tid) ? ((pp - tid + 255) >> 8) : 0;
        const float* fb = fp0 + (size_t)ymin * W + xmin;
        const unsigned spbase = (unsigned)__cvta_generic_to_shared(&patch[0][0]);

        #pragma unroll
        for (int ch = 0; ch < NCH; ch++) {
            const float* gch = fb + (size_t)ch * HW;
            #pragma unroll
            for (int s = 0; s < 4; s++)
                if (s < nslot)
                    cpa4(spbase + (unsigned)(tid + s * 256) * 16u + ch * 4u, gch + so[s]);
        }
        cpa_commit();

        #pragma unroll 1
        for (int ph = 0; ph < NPH; ph++) {
            const int buf = ph & 1;
            cpa_wait0();
            __syncthreads();

            if (ph + 1 < NPH) {
                const float* fbn = fb + (size_t)(ph + 1) * NCH * HW;
                unsigned db = spbase + (unsigned)(buf ^ 1) * (PSZ * 16u);
                #pragma unroll
                for (int ch = 0; ch < NCH; ch++) {
                    const float* gch = fbn + (size_t)ch * HW;
                    #pragma unroll
                    for (int s = 0; s < 4; s++)
                        if (s < nslot)
                            cpa4(db + (unsigned)(tid + s * 256) * 16u + ch * 4u, gch + so[s]);
                }
                cpa_commit();
            }

            if (tid < NPOS) {
                const float4* P = &patch[buf][0];
                float a0 = 0.f, a1 = 0.f, a2 = 0.f, a3 = 0.f;
                #pragma unroll
                for (int k = 0; k < 4; k++) {
                    int   ay  = ryo[k];
                    float wyk = wy[k];
                    #pragma unroll
                    for (int l = 0; l < 4; l++) {
                        float wgt = wyk * wx[l];
                        float4 v  = P[ay + rxo[l]];
                        a0 = fmaf(wgt, v.x, a0);
                        a1 = fmaf(wgt, v.y, a1);
                        a2 = fmaf(wgt, v.z, a2);
                        a3 = fmaf(wgt, v.w, a3);
                    }
                }
                int c0 = ph * NCH;
                op[(c0 + 0) * NPOS] = a0;
                op[(c0 + 1) * NPOS] = a1;
                op[(c0 + 2) * NPOS] = a2;
                op[(c0 + 3) * NPOS] = a3;
            }
        }
    } else {
        if (tid >= NPOS) return;
        const float* fp = fp0;
        #pragma unroll 1
        for (int c = 0; c < CQ; c++) {
            float acc = 0.f;
            #pragma unroll
            for (int k = 0; k < 4; k++) {
                int   ay  = ryo[k] * W;
                float wyk = wy[k];
                #pragma unroll
                for (int l = 0; l < 4; l++)
                    acc = fmaf(wyk * wx[l], __ldg(fp + ay + rxo[l]), acc);
            }
            op[c * NPOS] = acc;
            fp += HW;
        }
    }
}

extern "C" void kernel_launch(void* const* d_in, const int* in_sizes, int n_in,
                              void* d_out, int out_size)
{
    const float* p4     = (const float*)d_in[0];
    const float* p8     = (const float*)d_in[1];
    const float* p16    = (const float*)d_in[2];
    const float* p32    = (const float*)d_in[3];
    const float* boxes  = (const float*)d_in[4];
    const float* scores = (const float*)d_in[5];
    float* out = (float*)d_out;

    nms_rank_kernel<<<BB, NN>>>(boxes, scores);
    nms_mask_kernel<<<BB * 64, 256>>>();
    nms_scan_kernel<<<BB, NN>>>(out);
    pool_kernel<<<BB * NN * 4, 256>>>(p4, p8, p16, p32, out);
}